// round 17
// baseline (speedup 1.0000x reference)
#include <cuda_runtime.h>
#include <cuda_bf16.h>
#include <cstdint>
#include <math.h>

#define T_STEPS 512
#define BATCH 64
#define NHID 2048
#define NINP 64
#define NOUT 64
#define NB 128
#define NT 256
#define NFLAG 16

#define OFF_BHI 0          // 64KB: [ks64][lane32][8 u32] (4 n8-tiles x 2 regs)
#define OFF_BLO 65536
#define OFF_RED 131072     // 64KB: [w8][q16][lane32][4 f32]
#define SMEM_BYTES 196608

// State as A-fragment images: [buf][hi/lo][kt128][mt4][lane32][reg4] b32
__device__ unsigned g_A[2][2][128*4*32*4];
__device__ float    g_sfin[NHID*BATCH];
__device__ float    g_xT[T_STEPS*NINP*BATCH];
__device__ unsigned long long g_u[(size_t)T_STEPS*1024*64];   // [t][hp][b] f32x2 pairs
__device__ unsigned long long g_P[64][1024];                  // pair partials [hgrp][hp16*64+b]
__device__ unsigned g_prod[NFLAG*32];
__device__ unsigned g_pf[64*32];

__global__ void reset_kernel() {
    if (threadIdx.x < NFLAG) g_prod[threadIdx.x*32] = 0u;
    if (threadIdx.x < 64)    g_pf[threadIdx.x*32] = 0u;
}

__global__ void transpose_x_kernel(const float* __restrict__ x) {
    __shared__ float xs[BATCH*(NINP+1)];
    const int t = blockIdx.x;
    const float* xt = x + (size_t)t*(BATCH*NINP);
    for (int i = threadIdx.x; i < BATCH*NINP; i += blockDim.x)
        xs[(i>>6)*(NINP+1) + (i&63)] = xt[i];
    __syncthreads();
    float* dst = g_xT + (size_t)t*(NINP*BATCH);
    for (int i = threadIdx.x; i < NINP*BATCH; i += blockDim.x)
        dst[i] = xs[(i&63)*(NINP+1) + (i>>6)];
}

__device__ __forceinline__ unsigned long long pk2(float v) {
    unsigned long long r; asm("mov.b64 %0, {%1, %1};" : "=l"(r) : "f"(v)); return r;
}
__device__ __forceinline__ unsigned long long pk2b(float a, float b) {
    unsigned long long r; asm("mov.b64 %0, {%1, %2};" : "=l"(r) : "f"(a), "f"(b)); return r;
}
__device__ __forceinline__ void fma2(unsigned long long& d, unsigned long long a, unsigned long long b) {
    asm("fma.rn.f32x2 %0, %1, %2, %0;" : "+l"(d) : "l"(a), "l"(b));
}
__device__ __forceinline__ void addf2(unsigned long long& d, unsigned long long a) {
    asm("add.rn.f32x2 %0, %0, %1;" : "+l"(d) : "l"(a));
}
__device__ __forceinline__ void upk(unsigned long long v, float& lo, float& hi) {
    asm("mov.b64 {%0, %1}, %2;" : "=f"(lo), "=f"(hi) : "l"(v));
}
__device__ __forceinline__ void ldcg4(const unsigned* p, unsigned* r) {
    asm volatile("ld.global.cg.v4.u32 {%0,%1,%2,%3}, [%4];"
                 : "=r"(r[0]),"=r"(r[1]),"=r"(r[2]),"=r"(r[3]) : "l"(p));
}
__device__ __forceinline__ unsigned long long ldcg_u64(const unsigned long long* p) {
    unsigned long long r;
    asm volatile("ld.global.cg.u64 %0, [%1];" : "=l"(r) : "l"(p));
    return r;
}
__device__ __forceinline__ void stcg_u64(unsigned long long* p, unsigned long long v) {
    asm volatile("st.global.cg.u64 [%0], %1;" :: "l"(p), "l"(v) : "memory");
}
__device__ __forceinline__ void mmab(float* c, const unsigned* a, unsigned b0, unsigned b1) {
    asm volatile("mma.sync.aligned.m16n8k16.row.col.f32.bf16.bf16.f32 "
                 "{%0,%1,%2,%3}, {%4,%5,%6,%7}, {%8,%9}, {%0,%1,%2,%3};"
                 : "+f"(c[0]),"+f"(c[1]),"+f"(c[2]),"+f"(c[3])
                 : "r"(a[0]),"r"(a[1]),"r"(a[2]),"r"(a[3]), "r"(b0),"r"(b1));
}
__device__ __forceinline__ unsigned pkbf(float a, float b) {
    __nv_bfloat16 x = __float2bfloat16(a), y = __float2bfloat16(b);
    return (unsigned)__bfloat16_as_ushort(x) | ((unsigned)__bfloat16_as_ushort(y) << 16);
}

// ---- prologue: u[t][hp][b] pairs ----
__global__ void u_kernel(const float* __restrict__ Wi, const float* __restrict__ Wib) {
    extern __shared__ float usm[];
    float* xs = usm;
    unsigned long long* wip = (unsigned long long*)(usm + NINP*BATCH);
    const int t = blockIdx.x, hseg = blockIdx.y, tid = threadIdx.x;
    const float* xsrc = g_xT + (size_t)t*(NINP*BATCH);
    for (int i = tid; i < NINP*BATCH; i += 256) xs[i] = xsrc[i];
    for (int i = tid; i < NINP*64; i += 256) {
        int hpl = i & 63, ii = i >> 6;
        int h = (hseg*64 + hpl)*2;
        wip[ii*64 + hpl] = pk2b(Wi[(size_t)h*NINP + ii], Wi[(size_t)(h+1)*NINP + ii]);
    }
    __syncthreads();
    #pragma unroll
    for (int j = 0; j < 16; ++j) {
        int task = tid + j*256;
        int hpl = task >> 6, b = task & 63;
        int h = (hseg*64 + hpl)*2;
        unsigned long long u = pk2b(Wib[h], Wib[h+1]);
        #pragma unroll 8
        for (int i = 0; i < NINP; ++i)
            fma2(u, wip[i*64 + hpl], pk2(xs[i*BATCH + b]));
        g_u[((size_t)t*1024 + hseg*64 + hpl)*64 + b] = u;
    }
}

__global__ void __launch_bounds__(NT, 1) rnn_kernel(
    const float* __restrict__ Wh, const float* __restrict__ Ag,
    const float* __restrict__ Om)
{
    extern __shared__ char smem[];
    const int tid = threadIdx.x, wrp = tid >> 5, lane = tid & 31;
    const int bid = blockIdx.x;
    const int hgrp = bid >> 1, kh = bid & 1;     // 64 h-groups x 2 k-halves
    const int h0g = hgrp * 32;
    const int k0  = kh * 1024;

    // B fragments: 32 h (4 n8-tiles) x 1024 k (64 ksteps), proven layout extended to q=0..7
    for (int idx = tid; idx < 16384; idx += NT) {
        int q = idx & 7, ln = (idx >> 3) & 31, ks = idx >> 8;
        int h = (q >> 1) * 8 + (ln >> 2);
        int k = k0 + ks * 16 + (q & 1) * 8 + (ln & 3) * 2;
        float w0 = Wh[(size_t)(h0g + h) * NHID + k];
        float w1 = Wh[(size_t)(h0g + h) * NHID + k + 1];
        __nv_bfloat16 b0 = __float2bfloat16(w0), b1 = __float2bfloat16(w1);
        ((unsigned*)(smem + OFF_BHI))[(ks*32+ln)*8 + q] =
            (unsigned)__bfloat16_as_ushort(b0) | ((unsigned)__bfloat16_as_ushort(b1) << 16);
        ((unsigned*)(smem + OFF_BLO))[(ks*32+ln)*8 + q] =
            pkbf(w0 - __bfloat162float(b0), w1 - __bfloat162float(b1));
    }

    // epilogue slots (kh=0 only): thread -> hp = tid>>4 (0..15), b = (tid&15)*4 + j
    const int shp = tid >> 4, sb0 = (tid & 15) * 4;
    unsigned aoffs[4];
    #pragma unroll
    for (int j = 0; j < 4; ++j) {
        int b = sb0 + j;
        int kt = hgrp*2 + (shp >> 3);
        int el = shp & 7;
        int amt = b >> 4;
        int aln = (b & 7) * 4 + (el & 3);
        int areg = (((b & 15) >= 8) ? 1 : 0) + ((el >= 4) ? 2 : 0);
        aoffs[j] = (((unsigned)kt*4 + amt)*32 + aln)*4 + areg;
    }
    if (kh == 0) {
        #pragma unroll
        for (int j = 0; j < 4; ++j) { g_A[0][0][aoffs[j]] = 0x3F803F80u; g_A[0][1][aoffs[j]] = 0u; }
    }
    __syncthreads();
    if (kh == 0 && tid == 0) { __threadfence(); atomicAdd(&g_prod[(hgrp >> 2)*32], 1u); }

    float Ac[4][2], Oc[4][2], st[4][2];
    if (kh == 0) {
        #pragma unroll
        for (int j = 0; j < 4; ++j) {
            int h = h0g + shp*2;
            Ac[j][0] = Ag[h];   Ac[j][1] = Ag[h+1];
            Oc[j][0] = Om[h];   Oc[j][1] = Om[h+1];
            st[j][0] = 1.f;     st[j][1] = 1.f;
        }
    }

    const int fg  = kh*8 + ((wrp + hgrp) & 7);   // flag group == this warp's kt-slice producers
    const int ksb = ((wrp + hgrp) & 7) * 8;      // local kstep base (rotated)

    for (int t = 0; t < T_STEPS; ++t) {
        const int cur = t & 1, nxt = cur ^ 1;
        const unsigned epoch = (unsigned)(4 * (t + 1));

        {   // per-warp flag wait
            unsigned v;
            do { asm volatile("ld.acquire.gpu.u32 %0, [%1];" : "=r"(v) : "l"(&g_prod[fg*32]) : "memory"); }
            while (v < epoch);
        }

        float acc[16][4];
        #pragma unroll
        for (int q = 0; q < 16; ++q) { acc[q][0]=0.f; acc[q][1]=0.f; acc[q][2]=0.f; acc[q][3]=0.f; }

        const unsigned* gh = &g_A[cur][0][0];
        const unsigned* gl = &g_A[cur][1][0];
        #pragma unroll
        for (int j = 0; j < 8; ++j) {
            const int ks = ksb + j;                  // local kstep 0..63
            const int kt = kh*64 + ks;               // absolute kt
            const uint4* bhp = (const uint4*)(smem + OFF_BHI) + (ks*32 + lane)*2;
            const uint4* blp = (const uint4*)(smem + OFF_BLO) + (ks*32 + lane)*2;
            uint4 bh0 = bhp[0], bh1 = bhp[1];
            uint4 bl0 = blp[0], bl1 = blp[1];
            #pragma unroll
            for (int mt = 0; mt < 4; ++mt) {
                unsigned ah[4], al[4];
                const unsigned base = ((kt*4 + mt)*32 + lane)*4;
                ldcg4(gh + base, ah);
                ldcg4(gl + base, al);
                mmab(acc[mt*4+0], ah, bh0.x, bh0.y);
                mmab(acc[mt*4+0], ah, bl0.x, bl0.y);
                mmab(acc[mt*4+0], al, bh0.x, bh0.y);
                mmab(acc[mt*4+1], ah, bh0.z, bh0.w);
                mmab(acc[mt*4+1], ah, bl0.z, bl0.w);
                mmab(acc[mt*4+1], al, bh0.z, bh0.w);
                mmab(acc[mt*4+2], ah, bh1.x, bh1.y);
                mmab(acc[mt*4+2], ah, bl1.x, bl1.y);
                mmab(acc[mt*4+2], al, bh1.x, bh1.y);
                mmab(acc[mt*4+3], ah, bh1.z, bh1.w);
                mmab(acc[mt*4+3], ah, bl1.z, bl1.w);
                mmab(acc[mt*4+3], al, bh1.z, bh1.w);
            }
        }
        {   // partials to smem
            float4* rb = (float4*)(smem + OFF_RED);
            #pragma unroll
            for (int q = 0; q < 16; ++q)
                rb[(wrp*16 + q)*32 + lane] = make_float4(acc[q][0], acc[q][1], acc[q][2], acc[q][3]);
        }
        __syncthreads();

        // in-CTA reduce: thread sums its 4 slots over 8 warps
        unsigned long long psum[4];
        #pragma unroll
        for (int j = 0; j < 4; ++j) {
            int b = sb0 + j;
            int q = (b >> 4)*4 + (shp >> 2);
            int rl = (b & 7)*4 + (shp & 3);
            int rg = ((b & 15) >= 8) ? 1 : 0;        // u64 index within lane's 4 floats
            const unsigned long long* rp = (const unsigned long long*)(smem + OFF_RED)
                                           + ((size_t)q*32 + rl)*2 + rg;
            unsigned long long s = rp[0];
            #pragma unroll
            for (int w = 1; w < 8; ++w) s = (addf2(s, rp[(size_t)w*16*32*2]), s);
            psum[j] = s;
        }

        if (kh == 1) {
            // publish partial, signal pair flag
            unsigned long long* pp = &g_P[hgrp][shp*64 + sb0];
            #pragma unroll
            for (int j = 0; j < 4; ++j) stcg_u64(pp + j, psum[j]);
            __syncthreads();
            if (tid == 0) { __threadfence(); atomicAdd(&g_pf[hgrp*32], 1u); }
        } else {
            // u loads (overlap with peer wait)
            const unsigned long long* up = g_u + ((size_t)t*1024 + hgrp*16 + shp)*64 + sb0;
            unsigned long long uv[4];
            #pragma unroll
            for (int j = 0; j < 4; ++j) uv[j] = ldcg_u64(up + j);
            {   // wait peer partial
                unsigned v;
                do { asm volatile("ld.acquire.gpu.u32 %0, [%1];" : "=r"(v) : "l"(&g_pf[hgrp*32]) : "memory"); }
                while (v < (unsigned)(t + 1));
            }
            const unsigned long long* pp = &g_P[hgrp][shp*64 + sb0];
            #pragma unroll
            for (int j = 0; j < 4; ++j) addf2(psum[j], ldcg_u64(pp + j));

            #pragma unroll
            for (int j = 0; j < 4; ++j) {
                float m0, m1, u0, u1;
                upk(psum[j], m0, m1); upk(uv[j], u0, u1);
                float n0 = Ac[j][0] * cosf(Oc[j][0] * st[j][0] + u0) + m0;
                float n1 = Ac[j][1] * cosf(Oc[j][1] * st[j][1] + u1) + m1;
                st[j][0] = n0; st[j][1] = n1;
                __nv_bfloat16 h0 = __float2bfloat16(n0), h1 = __float2bfloat16(n1);
                g_A[nxt][0][aoffs[j]] = (unsigned)__bfloat16_as_ushort(h0) | ((unsigned)__bfloat16_as_ushort(h1) << 16);
                g_A[nxt][1][aoffs[j]] = pkbf(n0 - __bfloat162float(h0), n1 - __bfloat162float(h1));
                if (t == T_STEPS - 1) {
                    int b = sb0 + j, h = h0g + shp*2;
                    g_sfin[(size_t)h * BATCH + b] = n0;
                    g_sfin[(size_t)(h+1) * BATCH + b] = n1;
                }
            }
            __syncthreads();
            if (tid == 0) { __threadfence(); atomicAdd(&g_prod[(hgrp >> 2)*32], 1u); }
        }
    }
}

__device__ float g_rpart[8][NOUT][BATCH];
__global__ void readout_part(const float* __restrict__ Wr) {
    const int o = blockIdx.x >> 3, sl = blockIdx.x & 7, b = threadIdx.x;
    const float* wr = Wr + (size_t)o * NHID;
    float acc = 0.f;
    const int h0 = sl * (NHID/8);
    #pragma unroll 4
    for (int h = h0; h < h0 + NHID/8; ++h) acc += g_sfin[h*BATCH + b] * wr[h];
    g_rpart[sl][o][b] = acc;
}
__global__ void readout_comb(const float* __restrict__ Wrb, float* __restrict__ out) {
    const int o = blockIdx.x, b = threadIdx.x;
    float acc = Wrb[o];
    #pragma unroll
    for (int sl = 0; sl < 8; ++sl) acc += g_rpart[sl][o][b];
    out[b*NOUT + o] = acc;
}

extern "C" void kernel_launch(void* const* d_in, const int* in_sizes, int n_in,
                              void* d_out, int out_size) {
    const float* x   = (const float*)d_in[0];
    const float* Wi  = (const float*)d_in[1];
    const float* Wib = (const float*)d_in[2];
    const float* Wh  = (const float*)d_in[3];
    const float* A   = (const float*)d_in[4];
    const float* Om  = (const float*)d_in[5];
    const float* Wr  = (const float*)d_in[6];
    const float* Wrb = (const float*)d_in[7];
    cudaFuncSetAttribute(rnn_kernel, cudaFuncAttributeMaxDynamicSharedMemorySize, SMEM_BYTES);
    cudaFuncSetAttribute(u_kernel, cudaFuncAttributeMaxDynamicSharedMemorySize, 49152);
    reset_kernel<<<1, 64>>>();                              // launch 0
    transpose_x_kernel<<<T_STEPS, 256>>>(x);                // launch 1
    u_kernel<<<dim3(T_STEPS, 16), 256, 49152>>>(Wi, Wib);   // launch 2
    rnn_kernel<<<NB, NT, SMEM_BYTES>>>(Wh, A, Om);          // launch 3 (ncu target)
    readout_part<<<NOUT*8, BATCH>>>(Wr);                    // launch 4
    readout_comb<<<NOUT, BATCH>>>(Wrb, (float*)d_out);      // launch 5
}